// round 10
// baseline (speedup 1.0000x reference)
#include <cuda_runtime.h>
#include <cstdint>

// Beamform_1649267442279 — GB300 sm_103a — R10: cp.async double-buffered
// persistent streaming kernel. R7/R8/R9 established that register-resident
// MLP is capped by the occ*regs product (best: R8, DRAM 82.7%). cp.async
// decouples outstanding bytes from registers: while stage k computes, stage
// k+1's full 20KB tile is in flight per CTA (4 CTAs/SM -> ~80KB/SM in
// flight, >> bandwidth-delay product). Each HBM line is fetched exactly
// once, sector-complete (no more 4x per-line LDG re-touch through L1).
//
// Semantics: per channel s, blocks of 20 complex samples (40 floats).
// Block b, row r (0..3), col c (0..4):
//   re[r,c] = in_s[40b + 10r + 2c],  im[r,c] = in_s[40b + 10r + 2c + 1]
//   out[(s*Bc+b)*10 + c]     = sum_r br[r]*re - bi[r]*im
//   out[(s*Bc+b)*10 + 5 + c] = sum_r bi[r]*re + br[r]*im
// with br[r]=bf[2r], bi[r]=bf[2r+1].

#define THREADS      256
#define TILE_BLOCKS  128                    // beam blocks per tile
#define TILE_F4      (TILE_BLOCKS * 10)     // 1280 float4 = 20480 B
#define F4_PER_THR   (TILE_F4 / THREADS)    // 5

__device__ __forceinline__ void cp_async16(uint32_t saddr, const void* gptr) {
    asm volatile("cp.async.cg.shared.global [%0], [%1], 16;\n"
                 :: "r"(saddr), "l"(gptr));
}
__device__ __forceinline__ void cp_commit() {
    asm volatile("cp.async.commit_group;\n" ::: "memory");
}
__device__ __forceinline__ void cp_wait1() {
    asm volatile("cp.async.wait_group 1;\n" ::: "memory");
}

__device__ __forceinline__ void cmac4(float& re, float& im,
                                      const float4 w0, const float4 w1,
                                      const float2 v0, const float2 v1,
                                      const float2 v2, const float2 v3)
{
    re  = w0.x * v0.x - w0.y * v0.y;
    im  = w0.y * v0.x + w0.x * v0.y;
    re += w0.z * v1.x - w0.w * v1.y;
    im += w0.w * v1.x + w0.z * v1.y;
    re += w1.x * v2.x - w1.y * v2.y;
    im += w1.y * v2.x + w1.x * v2.y;
    re += w1.z * v3.x - w1.w * v3.y;
    im += w1.w * v3.x + w1.z * v3.y;
}

__global__ void __launch_bounds__(THREADS, 4)
beamform_kernel(const float* __restrict__ in0,
                const float* __restrict__ in1,
                const float* __restrict__ in2,
                const float* __restrict__ in3,
                const float* __restrict__ bf,
                float* __restrict__ out,
                int tiles_per_ch,     // ceil(Bc / TILE_BLOCKS)
                int blocks_per_ch,    // Bc
                int n_f4_per_ch)      // N / 4 floats4 per channel
{
    __shared__ float4 s_in[2][TILE_F4];      // 2 x 20480 B

    const int t  = threadIdx.x;
    const int ch = blockIdx.y;
    const float* __restrict__ in =
        (ch == 0) ? in0 : (ch == 1) ? in1 : (ch == 2) ? in2 : in3;

    const float4 w0 = __ldg((const float4*)bf);      // br0, bi0, br1, bi1
    const float4 w1 = __ldg((const float4*)bf + 1);  // br2, bi2, br3, bi3

    const uint32_t sbase =
        (uint32_t)__cvta_generic_to_shared(&s_in[0][0]) + (uint32_t)t * 16u;

    const int stride = gridDim.x;
    int tile = blockIdx.x;
    if (tile >= tiles_per_ch) return;

    // ---- issue helper (inlined): coalesced 512B/warp cp.async windows ----
    auto issue = [&](int tl, int buf) {
        const int f4_base = tl * TILE_F4;
        const float4* __restrict__ gsrc = (const float4*)in + f4_base;
        const uint32_t sb = sbase + (uint32_t)buf * (TILE_F4 * 16u);
        #pragma unroll
        for (int q = 0; q < F4_PER_THR; q++) {
            const int idx = t + q * THREADS;
            if (f4_base + idx < n_f4_per_ch)
                cp_async16(sb + (uint32_t)q * (THREADS * 16u), gsrc + idx);
        }
    };

    // prologue: stage 0
    issue(tile, 0);
    cp_commit();

    int buf = 0;
    for (; tile < tiles_per_ch; tile += stride) {
        const int next = tile + stride;
        if (next < tiles_per_ch) issue(next, buf ^ 1);
        cp_commit();
        cp_wait1();              // own groups: stage 'tile' complete
        __syncthreads();         // cross-thread smem visibility

        // ---- compute tile from smem ----
        const float2* __restrict__ s2 = (const float2*)&s_in[buf][0];
        const int n_task = (blocks_per_ch - tile * TILE_BLOCKS >= TILE_BLOCKS)
                         ? TILE_BLOCKS * 5
                         : (blocks_per_ch - tile * TILE_BLOCKS) * 5;
        #pragma unroll
        for (int k = 0; k < 3; k++) {
            const int task = t + k * THREADS;        // 0..639
            if (task < n_task && task < TILE_BLOCKS * 5) {
                const int b = task / 5;
                const int j = task - b * 5;
                const int base = b * 20 + j;
                const float2 v0 = s2[base];
                const float2 v1 = s2[base + 5];
                const float2 v2 = s2[base + 10];
                const float2 v3 = s2[base + 15];
                float re, im;
                cmac4(re, im, w0, w1, v0, v1, v2, v3);
                const size_t ob =
                    ((size_t)ch * blocks_per_ch + (size_t)tile * TILE_BLOCKS + b) * 10;
                __stcs(out + ob + j,     re);
                __stcs(out + ob + 5 + j, im);
            }
        }

        buf ^= 1;
        __syncthreads();         // protect old buf before next-iter issue
    }
}

extern "C" void kernel_launch(void* const* d_in, const int* in_sizes, int n_in,
                              void* d_out, int out_size)
{
    const float* in0 = (const float*)d_in[0];
    const float* in1 = (const float*)d_in[1];
    const float* in2 = (const float*)d_in[2];
    const float* in3 = (const float*)d_in[3];
    const float* bf  = (const float*)d_in[4];
    float* out = (float*)d_out;

    const int N  = in_sizes[0];                        // 20,000,000 floats / ch
    const int Bc = N / 40;                             // 500,000 blocks / ch
    const int tiles = (Bc + TILE_BLOCKS - 1) / TILE_BLOCKS;  // 3907

    // 148 SMs x 4 CTAs/SM = 592 resident CTAs, exactly one wave.
    dim3 grid(148, 4);
    beamform_kernel<<<grid, THREADS>>>(in0, in1, in2, in3, bf, out,
                                       tiles, Bc, N / 4);
}